// round 8
// baseline (speedup 1.0000x reference)
#include <cuda_runtime.h>
#include <cuda_fp16.h>

#define N_  32
#define C_  3
#define H_  224
#define W_  224
#define T_  17
#define HW_ (H_ * W_)
#define TILE_O 32

#define TROWS 45
#define TSTR  48                     // half2 entries per row (12 x STS.128)
#define CH_STR (TROWS * TSTR)        // 2160 entries per channel
#define ENT_MAX 46                   // max entry index ever read

// identical fp expression for corners and pixels -> exact monotone bbox
#define MAP_X(wf, hf) __fadd_rn(__fsub_rn(__fmul_rn(c,(wf)), __fmul_rn(s,(hf))), 111.5f)
#define MAP_Y(wf, hf) __fadd_rn(__fadd_rn(__fmul_rn(s,(wf)), __fmul_rn(c,(hf))), 111.5f)

__global__ __launch_bounds__(256, 8) void rot_tile_v7_kernel(
    const float* __restrict__ x,       // (N, C, H, W)
    const float* __restrict__ thetas,  // (N, T)
    float* __restrict__ out)           // (N, T, C, H, W)
{
    __shared__ __half2 tile[C_ * CH_STR];   // 25,920 B

    const int nt  = blockIdx.y;
    const int n   = nt / T_;
    const int tid = threadIdx.x;
    const int tx0 = (blockIdx.x % 7) * TILE_O;
    const int ty0 = (blockIdx.x / 7) * TILE_O;

    float s, c;
    sincosf(thetas[nt], &s, &c);

    // ---- input bbox from tile corners ----
    const float wfa = (float)tx0 - 111.5f;
    const float wfb = (float)(tx0 + TILE_O - 1) - 111.5f;
    const float hfa = (float)ty0 - 111.5f;
    const float hfb = (float)(ty0 + TILE_O - 1) - 111.5f;

    const float min_ix = fminf(fminf(MAP_X(wfa,hfa), MAP_X(wfb,hfa)),
                               fminf(MAP_X(wfa,hfb), MAP_X(wfb,hfb)));
    const float min_iy = fminf(fminf(MAP_Y(wfa,hfa), MAP_Y(wfb,hfa)),
                               fminf(MAP_Y(wfa,hfb), MAP_Y(wfb,hfb)));
    const int gx0 = (int)floorf(min_ix);
    const int gy0 = (int)floorf(min_iy);
    const int a0  = gx0 & ~3;          // 16B-aligned col origin

    // max float col read = ENT_MAX+1 = 47 < 48
    const bool interior = (gy0 >= 0) && (gy0 + TROWS - 1 <= H_ - 1) &&
                          (a0  >= 0) && (a0  + 47 <= W_ - 1);

    const int img_base = (n * C_) * HW_;
    const int lane = tid & 31;
    const int warp = tid >> 5;

    // ---- universal fill: float4 load + shfl -> 4 half2 entries (STS.128) ----
    {
        const int cbase = a0 + 4 * lane;                 // lane's 4-float group
        const bool vec_ok = (cbase >= 0) && (cbase + 3 <= W_ - 1);
        // clamped scalar indices (used only when !vec_ok)
        const int c0 = min(max(cbase,     0), W_ - 1);
        const int c1 = min(max(cbase + 1, 0), W_ - 1);
        const int c2 = min(max(cbase + 2, 0), W_ - 1);
        const int c3 = min(max(cbase + 3, 0), W_ - 1);

        for (int r = warp; r < TROWS; r += 8) {
            const int gr = min(max(gy0 + r, 0), H_ - 1);
            const float* src = x + img_base + gr * W_;
#pragma unroll
            for (int ch = 0; ch < C_; ch++) {
                const float* sc = src + ch * HW_;
                float4 v = make_float4(0.f, 0.f, 0.f, 0.f);
                if (lane < 13) {                  // lanes 0..12 load (12 = shfl src)
                    if (vec_ok) {
                        v = *reinterpret_cast<const float4*>(sc + cbase);
                    } else {
                        v.x = __ldg(sc + c0); v.y = __ldg(sc + c1);
                        v.z = __ldg(sc + c2); v.w = __ldg(sc + c3);
                    }
                }
                const float nxt = __shfl_down_sync(0xffffffffu, v.x, 1);
                if (lane < 12) {
                    __half2 h0 = __floats2half2_rn(v.x, v.y);
                    __half2 h1 = __floats2half2_rn(v.y, v.z);
                    __half2 h2 = __floats2half2_rn(v.z, v.w);
                    __half2 h3 = __floats2half2_rn(v.w, nxt);
                    uint4 e;
                    e.x = *reinterpret_cast<unsigned*>(&h0);
                    e.y = *reinterpret_cast<unsigned*>(&h1);
                    e.z = *reinterpret_cast<unsigned*>(&h2);
                    e.w = *reinterpret_cast<unsigned*>(&h3);
                    *reinterpret_cast<uint4*>(tile + ch * CH_STR + r * TSTR + 4 * lane) = e;
                }
            }
        }
    }
    __syncthreads();

    // ---- compute: thread = (row tid>>4, col pair), 2 row-steps ----
    const int orow = tid >> 4;           // 0..15
    const int ocol = (tid & 15) * 2;     // 0..30

    const float wf0 = (float)(tx0 + ocol) - 111.5f;
    const unsigned obase = (unsigned)nt * (C_ * HW_)
                         + (unsigned)(ty0 + orow) * W_ + (unsigned)(tx0 + ocol);

#pragma unroll
    for (int j = 0; j < 2; j++) {
        const int row = orow + 16 * j;
        const float hf = (float)(ty0 + row) - 111.5f;

        const float ixa = MAP_X(wf0, hf);
        const float iya = MAP_Y(wf0, hf);
        const float ixb = __fadd_rn(ixa, c);
        const float iyb = __fadd_rn(iya, s);

        float wA00, wA01, wA10, wA11, wB00, wB01, wB10, wB11;
        int aA, aB;
        {
            const float fxa = ixa - floorf(ixa);
            const float fya = iya - floorf(iya);
            const float fxb = ixb - floorf(ixb);
            const float fyb = iyb - floorf(iyb);
            const int ix0a = (int)floorf(ixa), iy0a = (int)floorf(iya);
            const int ix0b = (int)floorf(ixb), iy0b = (int)floorf(iyb);

            const float gxa = 1.0f - fxa, gya = 1.0f - fya;
            const float gxb = 1.0f - fxb, gyb = 1.0f - fyb;

            if (interior) {
                wA00 = gya * gxa; wA01 = gya * fxa; wA10 = fya * gxa; wA11 = fya * fxa;
                wB00 = gyb * gxb; wB01 = gyb * fxb; wB10 = fyb * gxb; wB11 = fyb * fxb;
                aA = (iy0a - gy0) * TSTR + (ix0a - a0);
                aB = (iy0b - gy0) * TSTR + (ix0b - a0);
            } else {
                const float vxa0 = (ix0a >= 0  && ix0a < W_)     ? 1.0f : 0.0f;
                const float vxa1 = (ix0a >= -1 && ix0a < W_ - 1) ? 1.0f : 0.0f;
                const float vya0 = (iy0a >= 0  && iy0a < H_)     ? 1.0f : 0.0f;
                const float vya1 = (iy0a >= -1 && iy0a < H_ - 1) ? 1.0f : 0.0f;
                const float vxb0 = (ix0b >= 0  && ix0b < W_)     ? 1.0f : 0.0f;
                const float vxb1 = (ix0b >= -1 && ix0b < W_ - 1) ? 1.0f : 0.0f;
                const float vyb0 = (iy0b >= 0  && iy0b < H_)     ? 1.0f : 0.0f;
                const float vyb1 = (iy0b >= -1 && iy0b < H_ - 1) ? 1.0f : 0.0f;
                wA00 = gya * gxa * (vya0 * vxa0); wA01 = gya * fxa * (vya0 * vxa1);
                wA10 = fya * gxa * (vya1 * vxa0); wA11 = fya * fxa * (vya1 * vxa1);
                wB00 = gyb * gxb * (vyb0 * vxb0); wB01 = gyb * fxb * (vyb0 * vxb1);
                wB10 = fyb * gxb * (vyb1 * vxb0); wB11 = fyb * fxb * (vyb1 * vxb1);
                aA = min(max(iy0a - gy0, 0), TROWS - 2) * TSTR
                   + min(max(ix0a - a0,  0), ENT_MAX);
                aB = min(max(iy0b - gy0, 0), TROWS - 2) * TSTR
                   + min(max(ix0b - a0,  0), ENT_MAX);
            }
        }

        const unsigned ob = obase + (unsigned)(16 * j) * W_;

#pragma unroll
        for (int ch = 0; ch < C_; ch++) {
            const __half2* t = tile + ch * CH_STR;
            const float2 tA0 = __half22float2(t[aA]);          // (t00, t01)
            const float2 tA1 = __half22float2(t[aA + TSTR]);   // (t10, t11)
            const float2 tB0 = __half22float2(t[aB]);
            const float2 tB1 = __half22float2(t[aB + TSTR]);
            float2 r2;
            r2.x = tA0.x * wA00 + tA0.y * wA01 + tA1.x * wA10 + tA1.y * wA11;
            r2.y = tB0.x * wB00 + tB0.y * wB01 + tB1.x * wB10 + tB1.y * wB11;
            *reinterpret_cast<float2*>(out + ob + (unsigned)ch * HW_) = r2;
        }
    }
}

extern "C" void kernel_launch(void* const* d_in, const int* in_sizes, int n_in,
                              void* d_out, int out_size) {
    const float* x      = (const float*)d_in[0];
    const float* thetas = (const float*)d_in[1];
    float* out          = (float*)d_out;

    dim3 block(256);
    dim3 grid(7 * 7, N_ * T_);   // 49 tiles x 544 rotations
    rot_tile_v7_kernel<<<grid, block>>>(x, thetas, out);
}

// round 10
// speedup vs baseline: 1.0591x; 1.0591x over previous
#include <cuda_runtime.h>
#include <cuda_fp16.h>

#define N_  32
#define C_  3
#define H_  224
#define W_  224
#define T_  17
#define HW_ (H_ * W_)
#define TILE_O 32

#define TROWS 45
#define TSTR  52                     // half2 entries per row (48 stored + 4 pad, mult of 4!)
#define CH_STR (TROWS * TSTR)        // 2340 entries/channel -> 28,080 B total

// identical fp expression for corners and pixels -> exact monotone bbox
#define MAP_X(wf, hf) __fadd_rn(__fsub_rn(__fmul_rn(c,(wf)), __fmul_rn(s,(hf))), 111.5f)
#define MAP_Y(wf, hf) __fadd_rn(__fadd_rn(__fmul_rn(s,(wf)), __fmul_rn(c,(hf))), 111.5f)

__global__ __launch_bounds__(256, 8) void rot_tile_v10_kernel(
    const float* __restrict__ x,       // (N, C, H, W)
    const float* __restrict__ thetas,  // (N, T)
    float* __restrict__ out)           // (N, T, C, H, W)
{
    __shared__ __half2 tile[C_ * CH_STR];   // 28,080 B

    const int nt  = blockIdx.y;
    const int n   = nt / T_;
    const int tid = threadIdx.x;
    const int tx0 = (blockIdx.x % 7) * TILE_O;
    const int ty0 = (blockIdx.x / 7) * TILE_O;

    float s, c;
    sincosf(thetas[nt], &s, &c);

    // ---- exact input bbox from tile corners ----
    const float wfa = (float)tx0 - 111.5f;
    const float wfb = (float)(tx0 + TILE_O - 1) - 111.5f;
    const float hfa = (float)ty0 - 111.5f;
    const float hfb = (float)(ty0 + TILE_O - 1) - 111.5f;

    const float min_ix = fminf(fminf(MAP_X(wfa,hfa), MAP_X(wfb,hfa)),
                               fminf(MAP_X(wfa,hfb), MAP_X(wfb,hfb)));
    const float min_iy = fminf(fminf(MAP_Y(wfa,hfa), MAP_Y(wfb,hfa)),
                               fminf(MAP_Y(wfa,hfb), MAP_Y(wfb,hfb)));
    const float max_ix = fmaxf(fmaxf(MAP_X(wfa,hfa), MAP_X(wfb,hfa)),
                               fmaxf(MAP_X(wfa,hfb), MAP_X(wfb,hfb)));
    const float max_iy = fmaxf(fmaxf(MAP_Y(wfa,hfa), MAP_Y(wfb,hfa)),
                               fmaxf(MAP_Y(wfa,hfb), MAP_Y(wfb,hfb)));

    const int gx0 = (int)floorf(min_ix);
    const int gy0 = (int)floorf(min_iy);
    const int gx1 = (int)floorf(max_ix);      // max ix0 over pixels
    const int gy1 = (int)floorf(max_iy);
    const int a0  = gx0 & ~3;                 // 16B-aligned col origin

    const int rows_needed = min(gy1 + 2 - gy0, TROWS);       // includes +1 tap row
    const int ents_needed = min(gx1 + 2 - a0,  48);          // entries 0..ents-1

    // all four taps of every pixel inside the image?
    const bool interior = (gx0 >= 0) && (gy0 >= 0) &&
                          (gx1 + 1 <= W_ - 1) && (gy1 + 1 <= H_ - 1);

    const int img_base = (n * C_) * HW_;
    const int lane = tid & 31;
    const int warp = tid >> 5;

    // ---- universal fill: aligned float4 + 1 scalar -> 4 half2 entries ----
    if (lane < ((ents_needed + 3) >> 2)) {
        const int cbase  = a0 + 4 * lane;
        const bool vec_ok = (cbase >= 0) && (cbase + 3 <= W_ - 1);
        const int c0 = min(max(cbase,     0), W_ - 1);
        const int c1 = min(max(cbase + 1, 0), W_ - 1);
        const int c2 = min(max(cbase + 2, 0), W_ - 1);
        const int c3 = min(max(cbase + 3, 0), W_ - 1);
        const int ce = min(max(cbase + 4, 0), W_ - 1);

        for (int r = warp; r < rows_needed; r += 8) {
            const int gr = min(max(gy0 + r, 0), H_ - 1);
            const float* src = x + img_base + gr * W_;
#pragma unroll
            for (int ch = 0; ch < C_; ch++) {
                const float* sc = src + ch * HW_;
                float4 v;
                if (vec_ok) {
                    v = *reinterpret_cast<const float4*>(sc + cbase);
                } else {
                    v.x = sc[c0]; v.y = sc[c1]; v.z = sc[c2]; v.w = sc[c3];
                }
                const float f4 = sc[ce];
                __half2 h0 = __floats2half2_rn(v.x, v.y);
                __half2 h1 = __floats2half2_rn(v.y, v.z);
                __half2 h2 = __floats2half2_rn(v.z, v.w);
                __half2 h3 = __floats2half2_rn(v.w, f4);
                uint4 e;
                e.x = *reinterpret_cast<unsigned*>(&h0);
                e.y = *reinterpret_cast<unsigned*>(&h1);
                e.z = *reinterpret_cast<unsigned*>(&h2);
                e.w = *reinterpret_cast<unsigned*>(&h3);
                *reinterpret_cast<uint4*>(tile + ch * CH_STR + r * TSTR + 4 * lane) = e;
            }
        }
    }
    __syncthreads();

    // ---- compute: thread = (row tid>>4, col pair), 2 row-steps ----
    const int orow = tid >> 4;           // 0..15
    const int ocol = (tid & 15) * 2;     // 0..30

    const float wf0 = (float)(tx0 + ocol) - 111.5f;
    const unsigned obase = (unsigned)nt * (C_ * HW_)
                         + (unsigned)(ty0 + orow) * W_ + (unsigned)(tx0 + ocol);

#pragma unroll
    for (int j = 0; j < 2; j++) {
        const int row = orow + 16 * j;
        const float hf = (float)(ty0 + row) - 111.5f;

        const float ixa = MAP_X(wf0, hf);
        const float iya = MAP_Y(wf0, hf);
        const float ixb = __fadd_rn(ixa, c);
        const float iyb = __fadd_rn(iya, s);

        const float fxa = ixa - floorf(ixa);
        const float fya = iya - floorf(iya);
        const float fxb = ixb - floorf(ixb);
        const float fyb = iyb - floorf(iyb);
        const int ix0a = (int)floorf(ixa), iy0a = (int)floorf(iya);
        const int ix0b = (int)floorf(ixb), iy0b = (int)floorf(iyb);

        const float gxa = 1.0f - fxa, gya = 1.0f - fya;
        const float gxb = 1.0f - fxb, gyb = 1.0f - fyb;

        // bbox exactness -> addresses always in stored range
        const int aA = (iy0a - gy0) * TSTR + (ix0a - a0);
        const int aB = (iy0b - gy0) * TSTR + (ix0b - a0);

        float wA00, wA01, wA10, wA11, wB00, wB01, wB10, wB11;
        if (interior) {
            wA00 = gya * gxa; wA01 = gya * fxa; wA10 = fya * gxa; wA11 = fya * fxa;
            wB00 = gyb * gxb; wB01 = gyb * fxb; wB10 = fyb * gxb; wB11 = fyb * fxb;
        } else {
            const float vxa0 = (ix0a >= 0  && ix0a < W_)     ? 1.0f : 0.0f;
            const float vxa1 = (ix0a >= -1 && ix0a < W_ - 1) ? 1.0f : 0.0f;
            const float vya0 = (iy0a >= 0  && iy0a < H_)     ? 1.0f : 0.0f;
            const float vya1 = (iy0a >= -1 && iy0a < H_ - 1) ? 1.0f : 0.0f;
            const float vxb0 = (ix0b >= 0  && ix0b < W_)     ? 1.0f : 0.0f;
            const float vxb1 = (ix0b >= -1 && ix0b < W_ - 1) ? 1.0f : 0.0f;
            const float vyb0 = (iy0b >= 0  && iy0b < H_)     ? 1.0f : 0.0f;
            const float vyb1 = (iy0b >= -1 && iy0b < H_ - 1) ? 1.0f : 0.0f;
            wA00 = gya * gxa * (vya0 * vxa0); wA01 = gya * fxa * (vya0 * vxa1);
            wA10 = fya * gxa * (vya1 * vxa0); wA11 = fya * fxa * (vya1 * vxa1);
            wB00 = gyb * gxb * (vyb0 * vxb0); wB01 = gyb * fxb * (vyb0 * vxb1);
            wB10 = fyb * gxb * (vyb1 * vxb0); wB11 = fyb * fxb * (vyb1 * vxb1);
        }

        const unsigned ob = obase + (unsigned)(16 * j) * W_;

#pragma unroll
        for (int ch = 0; ch < C_; ch++) {
            const __half2* t = tile + ch * CH_STR;
            const float2 tA0 = __half22float2(t[aA]);          // (t00, t01)
            const float2 tA1 = __half22float2(t[aA + TSTR]);   // (t10, t11)
            const float2 tB0 = __half22float2(t[aB]);
            const float2 tB1 = __half22float2(t[aB + TSTR]);
            float2 r2;
            r2.x = tA0.x * wA00 + tA0.y * wA01 + tA1.x * wA10 + tA1.y * wA11;
            r2.y = tB0.x * wB00 + tB0.y * wB01 + tB1.x * wB10 + tB1.y * wB11;
            *reinterpret_cast<float2*>(out + ob + (unsigned)ch * HW_) = r2;
        }
    }
}

extern "C" void kernel_launch(void* const* d_in, const int* in_sizes, int n_in,
                              void* d_out, int out_size) {
    const float* x      = (const float*)d_in[0];
    const float* thetas = (const float*)d_in[1];
    float* out          = (float*)d_out;

    dim3 block(256);
    dim3 grid(7 * 7, N_ * T_);   // 49 tiles x 544 rotations
    rot_tile_v10_kernel<<<grid, block>>>(x, thetas, out);
}